// round 17
// baseline (speedup 1.0000x reference)
#include <cuda_runtime.h>
#include <cstdint>

// (B, D, H, W) = (2, 192, 192, 192) fp32
#define DD 192
#define HH 192
#define WW 192
#define PLANE 36864
#define VOL   7077888

#define NT 256
#define INR 24
// raw stage: [2 sets][2 sl][2 fld][24][44]
#define ST_ROW 44
#define ST_FIELD 1056
#define ST_SLICE 2112
#define ST_PAIR 4224
// W-sums: [2 par][2 sl][3 fld][24][36]
#define WSTR 36
#define WFLD 864
#define WSL  2592
#define WPAR 5184
// HW-sums: [2 par][2 sl][3 fld][16][32]
#define HWSTR 32
#define HWFLD 512
#define HWSL  1536
#define HWPAR 3072

#define INV_VOL (1.0f/729.0f)
#define EPS 1e-5f

#define SMEM_FLOATS (2*ST_PAIR + 2*WPAR + 2*HWPAR)   // 24960
#define SMEM_BYTES  (SMEM_FLOATS*4)                  // 99840 -> 2 CTAs/SM

// R17: pair-batched pipeline w/ materialized HW-sums, all stages load-balanced.
// region i: fill(pair i+1) | D(pair i-2) | H(pair i-1) | W(pair i)
__global__ void __launch_bounds__(NT, 2)
lncc_fusedC(const float* __restrict__ gt, const float* __restrict__ gp,
            float* __restrict__ out)
{
    extern __shared__ float sm[];
    float* stg = sm;                      // raw pairs
    float* ws  = sm + 2*ST_PAIR;          // W-sums
    float* hw  = ws + 2*WPAR;             // HW-sums

    const int tid = threadIdx.x;
    const int bx = blockIdx.x;
    const int wt = bx % 6;
    const int ht = (bx/6) % 12;
    const int dc = (bx/72) % 2;
    const int bb = bx/144;
    const int w0 = wt*32, h0 = ht*16, d0 = dc*96;
    const int gvol = bb*VOL;

    // zero raw stages once: OOB (h/w halo) lanes are never overwritten
    for (int i = tid; i < 2*ST_PAIR; i += NT) stg[i] = 0.f;

    const uint32_t stg_base = (uint32_t)__cvta_generic_to_shared(stg);

    // ---- fill geometry: 480 tasks/slice = 48 rowf x 10 float4 chunks ----
    const float* fsrc[2]; uint32_t fdst[2]; bool fok[2];
#pragma unroll
    for (int k = 0; k < 2; ++k) {
        const int task = tid + k*NT;
        bool ok = task < 480;
        const int chunk = task % 10;
        const int rowf  = task / 10;
        const int fld   = rowf >= INR ? 1 : 0;
        const int row   = rowf - fld*INR;
        const int gh = h0 - 4 + row;
        const int gw = w0 - 4 + chunk*4;
        ok = ok && (unsigned)gh < HH && (unsigned)gw < WW;
        fok[k]  = ok;
        fsrc[k] = (fld ? gp : gt) + (gvol + gh*WW + gw);
        fdst[k] = stg_base + (uint32_t)(fld*ST_FIELD + row*ST_ROW + chunk*4)*4u;
    }

    auto fill_pair = [&](int p) {
        const uint32_t soff = (uint32_t)((p&1)*ST_PAIR)*4u;
#pragma unroll
        for (int sl = 0; sl < 2; ++sl) {
            const int dz = d0 - 4 + 2*p + sl;
            if ((unsigned)dz < DD) {
                const int off = dz*PLANE;
                const uint32_t dsb = soff + (uint32_t)(sl*ST_SLICE)*4u;
#pragma unroll
                for (int k = 0; k < 2; ++k)
                    if (fok[k])
                        asm volatile("cp.async.cg.shared.global [%0], [%1], 16;"
                                     :: "r"(fdst[k]+dsb), "l"(fsrc[k]+off));
            }
        }
        asm volatile("cp.async.commit_group;");
    };

    // ---- W geometry: 192 tasks/pair = 2 sl x 24 rows x 4 segs of 8 ----
    const bool wact = tid < 192;
    const int wsl  = tid >= 96 ? 1 : 0;
    const int wsub = tid - wsl*96;
    const int wr   = wsub >> 2, ws4 = wsub & 3;
    const int wroff = wsl*ST_SLICE + wr*ST_ROW + ws4*8;
    const int wcout = wsl*WSL + wr*WSTR + ws4*8;

    auto wstage = [&](int p) {
        if (!wact) return;
        const int dz = d0 - 4 + 2*p + wsl;
        float* o = ws + (p&1)*WPAR + wcout;
        if ((unsigned)dz < DD) {
            const float* pt = stg + (p&1)*ST_PAIR + wroff;
            const float4 T0 = ((const float4*)pt)[0];
            const float4 T1 = ((const float4*)pt)[1];
            const float4 T2 = ((const float4*)pt)[2];
            const float4 T3 = ((const float4*)pt)[3];
            const float* pq = pt + ST_FIELD;
            const float4 P0 = ((const float4*)pq)[0];
            const float4 P1 = ((const float4*)pq)[1];
            const float4 P2 = ((const float4*)pq)[2];
            const float4 P3 = ((const float4*)pq)[3];
            const float t[16] = {T0.x,T0.y,T0.z,T0.w, T1.x,T1.y,T1.z,T1.w,
                                 T2.x,T2.y,T2.z,T2.w, T3.x,T3.y,T3.z,T3.w};
            const float p2[16] = {P0.x,P0.y,P0.z,P0.w, P1.x,P1.y,P1.z,P1.w,
                                  P2.x,P2.y,P2.z,P2.w, P3.x,P3.y,P3.z,P3.w};
            float r[8];
            {   float s = 0.f;
#pragma unroll
                for (int k = 0; k < 9; ++k) s += t[k];
                r[0] = s;
#pragma unroll
                for (int q = 1; q < 8; ++q) { s += t[8+q] - t[q-1]; r[q] = s; }
                *(float4*)(o)     = make_float4(r[0],r[1],r[2],r[3]);
                *(float4*)(o + 4) = make_float4(r[4],r[5],r[6],r[7]);
            }
            {   float s = 0.f;
#pragma unroll
                for (int k = 0; k < 9; ++k) s += p2[k];
                r[0] = s;
#pragma unroll
                for (int q = 1; q < 8; ++q) { s += p2[8+q] - p2[q-1]; r[q] = s; }
                *(float4*)(o + WFLD)     = make_float4(r[0],r[1],r[2],r[3]);
                *(float4*)(o + WFLD + 4) = make_float4(r[4],r[5],r[6],r[7]);
            }
            {   float s = 0.f;
#pragma unroll
                for (int k = 0; k < 9; ++k) s = fmaf(t[k], p2[k], s);
                r[0] = s;
#pragma unroll
                for (int q = 1; q < 8; ++q) {
                    s = fmaf(t[8+q], p2[8+q], s);
                    s = fmaf(-t[q-1], p2[q-1], s);
                    r[q] = s;
                }
                *(float4*)(o + 2*WFLD)     = make_float4(r[0],r[1],r[2],r[3]);
                *(float4*)(o + 2*WFLD + 4) = make_float4(r[4],r[5],r[6],r[7]);
            }
        } else {
            const float4 z = make_float4(0.f,0.f,0.f,0.f);
            *(float4*)(o)              = z;
            *(float4*)(o + 4)          = z;
            *(float4*)(o + WFLD)       = z;
            *(float4*)(o + WFLD + 4)   = z;
            *(float4*)(o + 2*WFLD)     = z;
            *(float4*)(o + 2*WFLD + 4) = z;
        }
    };

    // ---- H geometry: 384 half-column tasks = [2 ch][2 sl][3 fld][32 c] ----
    // threads 0-191: 1 task (ch=0); threads 192-255: 3 tasks (ch=1).
    int h_rd[3], h_wr[3];
    {
        if (tid < 192) {
            const int sl = tid/96, r2 = tid%96;
            const int fld = r2 >> 5, c = r2 & 31;
            h_rd[0] = sl*WSL + fld*WFLD + c;              // ch0: rows 0..15
            h_wr[0] = sl*HWSL + fld*HWFLD + c;            // out rows 0..7
            h_rd[1] = h_rd[0]; h_wr[1] = h_wr[0];
            h_rd[2] = h_rd[0]; h_wr[2] = h_wr[0];
        } else {
#pragma unroll
            for (int m = 0; m < 3; ++m) {
                const int tp = (tid - 192) + 64*m;        // 0..191
                const int sl = tp/96, r2 = tp%96;
                const int fld = r2 >> 5, c = r2 & 31;
                h_rd[m] = sl*WSL + fld*WFLD + 8*WSTR + c; // ch1: rows 8..23
                h_wr[m] = sl*HWSL + fld*HWFLD + 8*HWSTR + c; // out rows 8..15
            }
        }
    }

    auto hchunk = [&](int par, int rd, int wr2) {
        const float* in = ws + par*WPAR + rd;
        float* o = hw + par*HWPAR + wr2;
        float u[16];
#pragma unroll
        for (int r = 0; r < 16; ++r) u[r] = in[r*WSTR];
        float s = ((u[0]+u[1])+(u[2]+u[3]))+((u[4]+u[5])+(u[6]+u[7]))+u[8];
        o[0] = s;
#pragma unroll
        for (int q = 1; q < 8; ++q) {
            s += u[8+q] - u[q-1];
            o[q*HWSTR] = s;
        }
    };

    auto hstage = [&](int p) {
        const int par = p & 1;
        if (tid < 192) {
            hchunk(par, h_rd[0], h_wr[0]);
        } else {
            hchunk(par, h_rd[0], h_wr[0]);
            hchunk(par, h_rd[1], h_wr[1]);
            hchunk(par, h_rd[2], h_wr[2]);
        }
    };

    // ---- D geometry: all threads, 2 h-rows each ----
    const int tx = tid & 31, ty = tid >> 5;
    const int rb = ty << 1;
    const int d_rd = rb*HWSTR + tx;
    const int obase = gvol + (h0 + rb)*WW + w0 + tx;

    float ring[48], S[6];
#pragma unroll
    for (int q = 0; q < 48; ++q) ring[q] = 0.f;
#pragma unroll
    for (int q = 0; q < 6; ++q) S[q] = 0.f;

#define D_INGEST(PAR, SL, PH, DOUT, DVAL) do {                               \
    const float* hb = hw + (PAR)*HWPAR + (SL)*HWSL + d_rd;                   \
    const float A0 = hb[0];                                                  \
    const float A1 = hb[HWFLD];                                              \
    const float A2 = hb[2*HWFLD];                                            \
    const float B0 = hb[HWSTR];                                              \
    const float B1 = hb[HWFLD + HWSTR];                                      \
    const float B2 = hb[2*HWFLD + HWSTR];                                    \
    S[0]+=A0; S[1]+=A1; S[2]+=A2; S[3]+=B0; S[4]+=B1; S[5]+=B2;              \
    if (DOUT) {                                                              \
        const float ca = S[2]-S[1]*S[0]*INV_VOL;                             \
        const float cb = S[5]-S[4]*S[3]*INV_VOL;                             \
        const int oo = obase + (DVAL)*PLANE;                                 \
        out[oo]    = fmaf(ca,ca,EPS);                                        \
        out[oo+WW] = fmaf(cb,cb,EPS);                                        \
    }                                                                        \
    S[0]-=ring[(PH)*6+0]; S[1]-=ring[(PH)*6+1]; S[2]-=ring[(PH)*6+2];        \
    S[3]-=ring[(PH)*6+3]; S[4]-=ring[(PH)*6+4]; S[5]-=ring[(PH)*6+5];        \
    ring[(PH)*6+0]=A0; ring[(PH)*6+1]=A1; ring[(PH)*6+2]=A2;                 \
    ring[(PH)*6+3]=B0; ring[(PH)*6+4]=B1; ring[(PH)*6+5]=B2;                 \
} while(0)

// region: II compile-time (= I mod 4), I runtime
#define REGION(II, I) do {                                                   \
    asm volatile("cp.async.wait_group 0;");                                  \
    __syncthreads();                                                         \
    if ((I) <= 50) fill_pair((I)+1);                                         \
    {                                                                        \
        const int p_ = (I) - 2;                                              \
        const bool dout = (I) >= 6;                                          \
        D_INGEST((II)&1, 0, (2*(II))&7,   dout, d0 + 2*p_ - 8);              \
        D_INGEST((II)&1, 1, (2*(II)+1)&7, dout, d0 + 2*p_ - 7);              \
    }                                                                        \
    if ((I) <= 52) hstage((I) - 1);                                          \
    if ((I) <= 51) wstage((I));                                              \
} while(0)

    __syncthreads();                 // raw zeros visible
    fill_pair(0);

    // region 0
    asm volatile("cp.async.wait_group 0;");
    __syncthreads();
    fill_pair(1);
    wstage(0);

    // region 1
    asm volatile("cp.async.wait_group 0;");
    __syncthreads();
    fill_pair(2);
    hstage(0);
    wstage(1);

    // main regions i = 2..53: D processes pairs 0..51 (slices 0..103)
    for (int bq = 0; bq < 13; ++bq) {
#pragma unroll
        for (int ii = 0; ii < 4; ++ii) {
            const int i = 2 + bq*4 + ii;
            REGION(ii, i);
        }
    }
#undef REGION
#undef D_INGEST
}

extern "C" void kernel_launch(void* const* d_in, const int* in_sizes, int n_in,
                              void* d_out, int out_size) {
    const float* y_true = (const float*)d_in[0];
    const float* y_pred = (const float*)d_in[1];
    float* out = (float*)d_out;

    cudaFuncSetAttribute(lncc_fusedC,
                         cudaFuncAttributeMaxDynamicSharedMemorySize, SMEM_BYTES);

    // 6 w-tiles x 12 h-tiles x 2 d-chunks x 2 batches = 288 blocks (2 CTAs/SM)
    lncc_fusedC<<<288, NT, SMEM_BYTES>>>(y_true, y_pred, out);
}